// round 3
// baseline (speedup 1.0000x reference)
#include <cuda_runtime.h>
#include <math.h>

#define Bsz 512
#define Tlen 256
#define Qd 64
#define EMBd 128
#define H1d 128
#define H2d 64
#define VOC 5000
#define Lsteps 29
#define LTEXT 30

// ---------------- scratch (static device allocations; no cudaMalloc) ----------------
__device__ float g_keyT[Bsz * Qd * Tlen];          // key transposed: [b][k][t]  (33.5 MB)
__device__ float g_gates1[Bsz * 4 * H1d];          // [b][512]
__device__ float g_gates2[Bsz * 4 * H2d];          // [b][256]
__device__ float g_h1[2][Bsz * H1d];
__device__ float g_c1[2][Bsz * H1d];
__device__ float g_h2[2][Bsz * H2d];
__device__ float g_c2[2][Bsz * H2d];
__device__ float g_ctx[2][Bsz * Qd];
__device__ float g_z[Bsz * Lsteps * (H2d + Qd)];   // staging [b][t][128] for final GEMM (7.6 MB)

__device__ __forceinline__ float sigf(float x) { return 1.f / (1.f + expf(-x)); }

// ---------------- init: zero parity-0 states ----------------
__global__ void k_init() {
    int i = blockIdx.x * blockDim.x + threadIdx.x;
    if (i < Bsz * H1d) { g_h1[0][i] = 0.f; g_c1[0][i] = 0.f; }
    if (i < Bsz * H2d) { g_h2[0][i] = 0.f; g_c2[0][i] = 0.f; g_ctx[0][i] = 0.f; }
}

// ---------------- transpose key[t][b][k] -> keyT[b][k][t] ----------------
__global__ void k_transpose(const float* __restrict__ key) {
    __shared__ float s[64][65];
    int b = blockIdx.y;
    int t0 = blockIdx.x * 64;
    int tid = threadIdx.x;
    int c = tid & 63, r4 = tid >> 6;
#pragma unroll
    for (int pp = 0; pp < 16; pp++) {
        int tl = r4 + pp * 4;
        s[tl][c] = key[((t0 + tl) * Bsz + b) * Qd + c];
    }
    __syncthreads();
#pragma unroll
    for (int pp = 0; pp < 16; pp++) {
        int kl = r4 + pp * 4;
        g_keyT[(b * Qd + kl) * Tlen + t0 + c] = s[c][kl];
    }
}

// ---------------- K1: gates1 = [emb(x) | ctx | h1] @ [W_ih1 | W_hh1]^T + biases ----------------
// grid: (8 gate-tiles of 64, 16 batch-tiles of 32), 256 threads
__global__ void k_lstm1(const int* __restrict__ text, const float* __restrict__ emb,
                        const float* __restrict__ Wih1, const float* __restrict__ Whh1,
                        const float* __restrict__ bih1, const float* __restrict__ bhh1,
                        int t, int p) {
    __shared__ float As[32][33];   // [b][k]
    __shared__ float Ws[64][33];   // [g][k]
    __shared__ int   toks[32];
    int g0 = blockIdx.x * 64, b0 = blockIdx.y * 32;
    int tid = threadIdx.x;
    if (tid < 32) toks[tid] = text[(b0 + tid) * LTEXT + t];
    __syncthreads();

    int tx = tid & 15, ty = tid >> 4;
    float acc[2][4] = {};
    int kk = tid & 31;
    int lane8 = tid >> 5;
    const float* h1p  = g_h1[p];
    const float* ctxp = g_ctx[p];

    for (int c = 0; c < 10; c++) {   // K = 320 = 10 chunks of 32
        int kg = c * 32 + kk;
#pragma unroll
        for (int pp = 0; pp < 4; pp++) {
            int bl = lane8 + pp * 8;
            float v;
            if (kg < 128)      v = emb[toks[bl] * EMBd + kg];
            else if (kg < 192) v = ctxp[(b0 + bl) * Qd + (kg - 128)];
            else               v = h1p[(b0 + bl) * H1d + (kg - 192)];
            As[bl][kk] = v;
        }
#pragma unroll
        for (int pp = 0; pp < 8; pp++) {
            int gl = lane8 + pp * 8;
            float v;
            if (kg < 192) v = Wih1[(g0 + gl) * 192 + kg];
            else          v = Whh1[(g0 + gl) * 128 + (kg - 192)];
            Ws[gl][kk] = v;
        }
        __syncthreads();
#pragma unroll
        for (int k2 = 0; k2 < 32; k2++) {
            float a0 = As[ty * 2][k2], a1 = As[ty * 2 + 1][k2];
#pragma unroll
            for (int j = 0; j < 4; j++) {
                float w = Ws[j * 16 + tx][k2];
                acc[0][j] += a0 * w;
                acc[1][j] += a1 * w;
            }
        }
        __syncthreads();
    }
#pragma unroll
    for (int i = 0; i < 2; i++) {
        int b = b0 + ty * 2 + i;
#pragma unroll
        for (int j = 0; j < 4; j++) {
            int g = g0 + j * 16 + tx;
            g_gates1[b * 512 + g] = acc[i][j] + bih1[g] + bhh1[g];
        }
    }
}

// ---------------- K2: LSTM1 activation (h1,c1) + gates2 GEMM ----------------
// grid: (8 gate-tiles of 32, 16 batch-tiles of 32), 256 threads
__global__ void k_lstm2(const float* __restrict__ Wih2, const float* __restrict__ Whh2,
                        const float* __restrict__ bih2, const float* __restrict__ bhh2,
                        int p) {
    __shared__ float h1s[32][129];   // [b][u]  new h1
    __shared__ float h2s[32][65];    // [b][j]  prev h2
    __shared__ float W2s[32][65];    // [g][k-chunk]
    int g0 = blockIdx.x * 32, b0 = blockIdx.y * 32;
    int tid = threadIdx.x;
    const float* c1p = g_c1[p];
    float* h1n = g_h1[1 - p];
    float* c1n = g_c1[1 - p];

    // load prev h2 tile
    {
        int j = tid & 63, bl4 = tid >> 6;
#pragma unroll
        for (int pp = 0; pp < 8; pp++) {
            int bl = bl4 + pp * 4;
            h2s[bl][j] = g_h2[p][(b0 + bl) * H2d + j];
        }
    }
    // LSTM1 activation for this batch tile
    {
        int u = tid & 127, bl2 = tid >> 7;
#pragma unroll
        for (int pp = 0; pp < 16; pp++) {
            int bl = bl2 + pp * 2;
            int b = b0 + bl;
            float gi = g_gates1[b * 512 + u];
            float gf = g_gates1[b * 512 + 128 + u];
            float gg = g_gates1[b * 512 + 256 + u];
            float go = g_gates1[b * 512 + 384 + u];
            float c = sigf(gf) * c1p[b * H1d + u] + sigf(gi) * tanhf(gg);
            float h = sigf(go) * tanhf(c);
            h1s[bl][u] = h;
            if (blockIdx.x == 0) { h1n[b * H1d + u] = h; c1n[b * H1d + u] = c; }
        }
    }
    __syncthreads();

    int tx = tid & 15, ty = tid >> 4;
    float acc[2][2] = {};
    int kk = tid & 63, gl4 = tid >> 6;
    for (int kc = 0; kc < 3; kc++) {   // K = 192 = 3 chunks of 64 (2x h1, 1x h2)
#pragma unroll
        for (int pp = 0; pp < 8; pp++) {
            int gl = gl4 + pp * 4;
            float v;
            if (kc < 2) v = Wih2[(g0 + gl) * 128 + kc * 64 + kk];
            else        v = Whh2[(g0 + gl) * 64 + kk];
            W2s[gl][kk] = v;
        }
        __syncthreads();
        if (kc < 2) {
#pragma unroll
            for (int k2 = 0; k2 < 64; k2++) {
                float a0 = h1s[ty * 2][kc * 64 + k2], a1 = h1s[ty * 2 + 1][kc * 64 + k2];
                float w0 = W2s[tx][k2], w1 = W2s[16 + tx][k2];
                acc[0][0] += a0 * w0; acc[0][1] += a0 * w1;
                acc[1][0] += a1 * w0; acc[1][1] += a1 * w1;
            }
        } else {
#pragma unroll
            for (int k2 = 0; k2 < 64; k2++) {
                float a0 = h2s[ty * 2][k2], a1 = h2s[ty * 2 + 1][k2];
                float w0 = W2s[tx][k2], w1 = W2s[16 + tx][k2];
                acc[0][0] += a0 * w0; acc[0][1] += a0 * w1;
                acc[1][0] += a1 * w0; acc[1][1] += a1 * w1;
            }
        }
        __syncthreads();
    }
#pragma unroll
    for (int i = 0; i < 2; i++) {
        int b = b0 + ty * 2 + i;
#pragma unroll
        for (int j = 0; j < 2; j++) {
            int g = g0 + j * 16 + tx;
            g_gates2[b * 256 + g] = acc[i][j] + bih2[g] + bhh2[g];
        }
    }
}

// ---------------- K3: LSTM2 activation + q + attention + ctx (1 CTA per batch row) ----------------
__global__ void k_attn(const float* __restrict__ values, const float* __restrict__ mask,
                       const float* __restrict__ Wq, const float* __restrict__ bq,
                       int t, int p) {
    __shared__ float Wqs[64][65];
    __shared__ float h2sh[64];
    __shared__ float qs[64];
    __shared__ float ma[256];
    __shared__ float red[128];
    int b = blockIdx.x, tid = threadIdx.x;

    // LSTM2 activation
    if (tid < 64) {
        float gi = g_gates2[b * 256 + tid];
        float gf = g_gates2[b * 256 + 64 + tid];
        float gg = g_gates2[b * 256 + 128 + tid];
        float go = g_gates2[b * 256 + 192 + tid];
        float c = sigf(gf) * g_c2[p][b * H2d + tid] + sigf(gi) * tanhf(gg);
        float h = sigf(go) * tanhf(c);
        g_c2[1 - p][b * H2d + tid] = c;
        g_h2[1 - p][b * H2d + tid] = h;
        h2sh[tid] = h;
        g_z[(b * Lsteps + t) * 128 + tid] = h;
    }
    // stage W_q (coalesced)
#pragma unroll
    for (int pp = 0; pp < 32; pp++) {
        int idx = pp * 128 + tid;
        Wqs[idx >> 6][idx & 63] = Wq[idx];
    }
    __syncthreads();

    // q = h2 @ W_q^T + b_q
    if (tid < 64) {
        float a = bq[tid];
#pragma unroll
        for (int j = 0; j < 64; j++) a += h2sh[j] * Wqs[tid][j];
        qs[tid] = a;
    }
    __syncthreads();

    // energy over T=256 (2 per thread), coalesced via keyT[b][k][t]
    float e0 = 0.f, e1 = 0.f;
    const float* kb = g_keyT + b * (Qd * Tlen);
#pragma unroll 8
    for (int k = 0; k < 64; k++) {
        float qv = qs[k];
        e0 += qv * kb[k * 256 + tid];
        e1 += qv * kb[k * 256 + 128 + tid];
    }
    // softmax: max
    red[tid] = fmaxf(e0, e1);
    __syncthreads();
    for (int s = 64; s > 0; s >>= 1) { if (tid < s) red[tid] = fmaxf(red[tid], red[tid + s]); __syncthreads(); }
    float mx = red[0];
    __syncthreads();
    float w0 = expf(e0 - mx), w1 = expf(e1 - mx);
    red[tid] = w0 + w1;
    __syncthreads();
    for (int s = 64; s > 0; s >>= 1) { if (tid < s) red[tid] += red[tid + s]; __syncthreads(); }
    float S1 = red[0];
    __syncthreads();
    float mk0 = mask[b * 256 + tid], mk1 = mask[b * 256 + 128 + tid];
    float mw0 = mk0 * w0, mw1 = mk1 * w1;
    red[tid] = mw0 + mw1;
    __syncthreads();
    for (int s = 64; s > 0; s >>= 1) { if (tid < s) red[tid] += red[tid + s]; __syncthreads(); }
    float S2 = red[0];
    __syncthreads();
    // ma = (m*attn) / max(sum(m*attn), 2e-30)  where attn = w/S1; sum(m*attn) = S2/S1
    float r = S2 / S1;
    float D = fmaxf(r, 2e-30f);
    float scale = 1.f / (S1 * D);
    ma[tid] = mw0 * scale;
    ma[128 + tid] = mw1 * scale;
    __syncthreads();

    // ctx[v] = sum_t ma[t] * values[t][b][v]   (split t-range over two half-warpsgroups)
    int v = tid & 63, half = tid >> 6;
    float acc = 0.f;
    const float* vb = values + b * Qd + v;
    int base = half * 128;
#pragma unroll 4
    for (int ttk = 0; ttk < 128; ttk++) {
        acc += ma[base + ttk] * vb[(size_t)(base + ttk) * (Bsz * Qd)];
    }
    red[tid] = acc;
    __syncthreads();
    if (tid < 64) {
        float c = red[tid] + red[tid + 64];
        g_ctx[1 - p][b * Qd + tid] = c;
        g_z[(b * Lsteps + t) * 128 + 64 + tid] = c;
    }
}

// ---------------- K4: final GEMM  out[b][t][v] = z[b][t][:] . W_out[v][:] + b_out[v] ----------------
// M = 14848 rows (r = b*29+t), N = 5000, K = 128. 64x64 tiles, 256 threads, 4x4 micro.
__global__ void k_out(const float* __restrict__ Wout, const float* __restrict__ bout,
                      float* __restrict__ out) {
    __shared__ float As[64][65];
    __shared__ float Bs[64][65];
    int n0 = blockIdx.x * 64, m0 = blockIdx.y * 64;
    int tid = threadIdx.x;
    int tx = tid & 15, ty = tid >> 4;
    float acc[4][4] = {};
    int kk = tid & 63, rl4 = tid >> 6;

    for (int kc = 0; kc < 2; kc++) {
#pragma unroll
        for (int pp = 0; pp < 16; pp++) {
            int rl = rl4 + pp * 4;
            As[rl][kk] = g_z[(m0 + rl) * 128 + kc * 64 + kk];
            int col = n0 + rl;
            Bs[rl][kk] = (col < VOC) ? Wout[col * 128 + kc * 64 + kk] : 0.f;
        }
        __syncthreads();
#pragma unroll
        for (int k2 = 0; k2 < 64; k2++) {
            float a[4], bb[4];
#pragma unroll
            for (int i = 0; i < 4; i++) a[i] = As[i * 16 + ty][k2];
#pragma unroll
            for (int j = 0; j < 4; j++) bb[j] = Bs[j * 16 + tx][k2];
#pragma unroll
            for (int i = 0; i < 4; i++)
#pragma unroll
                for (int j = 0; j < 4; j++)
                    acc[i][j] += a[i] * bb[j];
        }
        __syncthreads();
    }
#pragma unroll
    for (int j = 0; j < 4; j++) {
        int col = n0 + j * 16 + tx;
        if (col < VOC) {
            float bo = bout[col];
#pragma unroll
            for (int i = 0; i < 4; i++) {
                int row = m0 + i * 16 + ty;
                out[(size_t)row * VOC + col] = acc[i][j] + bo;
            }
        }
    }
}

// ---------------- launcher ----------------
extern "C" void kernel_launch(void* const* d_in, const int* in_sizes, int n_in,
                              void* d_out, int out_size) {
    const float* key    = (const float*)d_in[0];
    const float* values = (const float*)d_in[1];
    const float* mask   = (const float*)d_in[2];
    const int*   text   = (const int*)d_in[3];
    const float* emb    = (const float*)d_in[4];
    const float* Wih1   = (const float*)d_in[5];
    const float* Whh1   = (const float*)d_in[6];
    const float* bih1   = (const float*)d_in[7];
    const float* bhh1   = (const float*)d_in[8];
    const float* Wih2   = (const float*)d_in[9];
    const float* Whh2   = (const float*)d_in[10];
    const float* bih2   = (const float*)d_in[11];
    const float* bhh2   = (const float*)d_in[12];
    const float* Wq     = (const float*)d_in[13];
    const float* bq     = (const float*)d_in[14];
    const float* Wout   = (const float*)d_in[15];
    const float* bout   = (const float*)d_in[16];
    float* out = (float*)d_out;

    k_init<<<256, 256>>>();
    k_transpose<<<dim3(4, Bsz), 256>>>(key);
    for (int t = 0; t < Lsteps; t++) {
        int p = t & 1;
        k_lstm1<<<dim3(8, 16), 256>>>(text, emb, Wih1, Whh1, bih1, bhh1, t, p);
        k_lstm2<<<dim3(8, 16), 256>>>(Wih2, Whh2, bih2, bhh2, p);
        k_attn<<<Bsz, 128>>>(values, mask, Wq, bq, t, p);
    }
    k_out<<<dim3(79, 232), 256>>>(Wout, bout, out);
}

// round 6
// speedup vs baseline: 1.0319x; 1.0319x over previous
#include <cuda_runtime.h>
#include <math.h>

#define Bsz 512
#define Tlen 256
#define Qd 64
#define EMBd 128
#define H1d 128
#define H2d 64
#define VOC 5000
#define Lsteps 29
#define LTEXT 30
#define NCTA 128

// ---------------- persistent scratch ----------------
__device__ float g_keyT[Bsz * Qd * Tlen];      // [b][k][t]
__device__ float g_W1p[512 * 320];             // permuted LSTM1 weights [4u+q][k]
__device__ float g_b1p[512];
__device__ float g_W2p[256 * 192];             // permuted LSTM2 weights
__device__ float g_b2p[256];
__device__ float g_WqT[64 * 64];               // WqT[u][j]
__device__ float g_h1[2][Bsz * H1d];
__device__ float g_c1[Bsz * H1d];
__device__ float g_h2[2][Bsz * H2d];
__device__ float g_c2[Bsz * H2d];
__device__ float g_ctx[Bsz * Qd];
__device__ float g_z[Bsz * Lsteps * 128];      // [b][t][h2|ctx]
__device__ unsigned g_cnt = 0;
__device__ volatile unsigned g_sense = 0;

__device__ __forceinline__ float sigf(float x) { return 1.f / (1.f + expf(-x)); }

// sense-reversal grid barrier (persistent-safe across graph replays:
// count self-resets; sense is sampled at kernel start)
__device__ __forceinline__ void gbar(unsigned& sense) {
    __syncthreads();
    if (threadIdx.x == 0) {
        __threadfence();
        unsigned target = sense ^ 1u;
        sense = target;
        if (atomicAdd(&g_cnt, 1u) == NCTA - 1) {
            g_cnt = 0;
            __threadfence();
            g_sense = target;
        } else {
            while (g_sense != target) { __nanosleep(32); }
        }
        __threadfence();
    }
    __syncthreads();
}

union SmemU {
    struct { float As[32][33]; float Ws[64][33]; float sg[32][65]; int toks[32]; } p1;
    struct { float As[32][33]; float Ws[32][33]; float sg[32][33]; } p2;
    struct { float h2[4][64]; float q[4][64]; float ma[4][256]; float ct[4][4][64]; float red[32]; } p3;
    float tr[64][65];
};

__global__ void __launch_bounds__(256, 1)
k_recur(const float* __restrict__ key, const float* __restrict__ values,
        const float* __restrict__ mask, const int* __restrict__ text,
        const float* __restrict__ emb,
        const float* __restrict__ Wih1, const float* __restrict__ Whh1,
        const float* __restrict__ bih1, const float* __restrict__ bhh1,
        const float* __restrict__ Wih2, const float* __restrict__ Whh2,
        const float* __restrict__ bih2, const float* __restrict__ bhh2,
        const float* __restrict__ Wq, const float* __restrict__ bq) {
    __shared__ SmemU su;
    int c = blockIdx.x, tid = threadIdx.x;
    unsigned sense = g_sense;   // sample before any barrier activity
    int gid = c * 256 + tid;

    // ================= prologue =================
    for (int i = gid; i < Bsz * H1d; i += NCTA * 256) { g_h1[0][i] = 0.f; g_h1[1][i] = 0.f; g_c1[i] = 0.f; }
    for (int i = gid; i < Bsz * H2d; i += NCTA * 256) { g_h2[0][i] = 0.f; g_h2[1][i] = 0.f; g_c2[i] = 0.f; g_ctx[i] = 0.f; }
    for (int i = gid; i < 512 * 320; i += NCTA * 256) {
        int r = i / 320, k = i - r * 320;
        int u = r >> 2, q = r & 3, orow = q * 128 + u;
        g_W1p[i] = (k < 192) ? Wih1[orow * 192 + k] : Whh1[orow * 128 + (k - 192)];
    }
    for (int i = gid; i < 512; i += NCTA * 256) {
        int u = i >> 2, q = i & 3;
        g_b1p[i] = bih1[q * 128 + u] + bhh1[q * 128 + u];
    }
    for (int i = gid; i < 256 * 192; i += NCTA * 256) {
        int r = i / 192, k = i - r * 192;
        int u = r >> 2, q = r & 3, orow = q * 64 + u;
        g_W2p[i] = (k < 128) ? Wih2[orow * 128 + k] : Whh2[orow * 64 + (k - 128)];
    }
    for (int i = gid; i < 256; i += NCTA * 256) {
        int u = i >> 2, q = i & 3;
        g_b2p[i] = bih2[q * 64 + u] + bhh2[q * 64 + u];
    }
    for (int i = gid; i < 64 * 64; i += NCTA * 256) {
        int u = i >> 6, j = i & 63;
        g_WqT[i] = Wq[j * 64 + u];
    }
    // keyT transpose: 2048 (b, t-block) tiles, 16 per CTA
    for (int it = 0; it < 16; it++) {
        int tix = c * 16 + it;
        int b = tix >> 2, t0 = (tix & 3) * 64;
        int cc = tid & 63, r4 = tid >> 6;
        __syncthreads();
#pragma unroll
        for (int pp = 0; pp < 16; pp++) {
            int tl = r4 + pp * 4;
            su.tr[tl][cc] = key[((t0 + tl) * Bsz + b) * Qd + cc];
        }
        __syncthreads();
#pragma unroll
        for (int pp = 0; pp < 16; pp++) {
            int kl = r4 + pp * 4;
            g_keyT[(b * Qd + kl) * Tlen + t0 + cc] = su.tr[cc][kl];
        }
    }
    gbar(sense);

    // partitions
    int gt = c & 7, bt = c >> 3;
    int b0p1 = bt * 32, pg0 = gt * 64, u0 = gt * 16;     // P1
    int pg02 = gt * 32, u02 = gt * 8;                     // P2 (same bt)
    int b0p3 = c * 4;                                     // P3

    // ================= recurrence =================
    for (int t = 0; t < Lsteps; t++) {
        int rp = t & 1, wp = rp ^ 1;

        // ---- P1: gates1 GEMM (32b x 64g permuted, K=320) + LSTM1 activation ----
        {
            if (tid < 32) su.p1.toks[tid] = text[(b0p1 + tid) * LTEXT + t];
            __syncthreads();
            float acc[2][4] = {};
            int tx = tid & 15, ty = tid >> 4, kk = tid & 31, lane8 = tid >> 5;
            for (int ch = 0; ch < 10; ch++) {
                int kg = ch * 32 + kk;
#pragma unroll
                for (int pp = 0; pp < 4; pp++) {
                    int bl = lane8 + pp * 8, b = b0p1 + bl;
                    float v;
                    if (kg < 128)      v = emb[su.p1.toks[bl] * EMBd + kg];
                    else if (kg < 192) v = __ldcg(&g_ctx[b * Qd + (kg - 128)]);
                    else               v = __ldcg(&g_h1[rp][b * H1d + (kg - 192)]);
                    su.p1.As[bl][kk] = v;
                }
#pragma unroll
                for (int pp = 0; pp < 8; pp++) {
                    int gl = lane8 + pp * 8;
                    su.p1.Ws[gl][kk] = g_W1p[(pg0 + gl) * 320 + kg];
                }
                __syncthreads();
#pragma unroll
                for (int k2 = 0; k2 < 32; k2++) {
                    float a0 = su.p1.As[ty * 2][k2], a1 = su.p1.As[ty * 2 + 1][k2];
#pragma unroll
                    for (int j = 0; j < 4; j++) {
                        float w = su.p1.Ws[j * 16 + tx][k2];
                        acc[0][j] += a0 * w;
                        acc[1][j] += a1 * w;
                    }
                }
                __syncthreads();
            }
#pragma unroll
            for (int i = 0; i < 2; i++)
#pragma unroll
                for (int j = 0; j < 4; j++)
                    su.p1.sg[ty * 2 + i][j * 16 + tx] = acc[i][j] + g_b1p[pg0 + j * 16 + tx];
            __syncthreads();
#pragma unroll
            for (int rep = 0; rep < 2; rep++) {
                int idx = tid + rep * 256;
                int bl = idx & 31, ul = idx >> 5;
                float gi = su.p1.sg[bl][4 * ul], gf = su.p1.sg[bl][4 * ul + 1];
                float gg = su.p1.sg[bl][4 * ul + 2], go = su.p1.sg[bl][4 * ul + 3];
                int b = b0p1 + bl, u = u0 + ul;
                float c1n = sigf(gf) * g_c1[b * H1d + u] + sigf(gi) * tanhf(gg);
                float h1n = sigf(go) * tanhf(c1n);
                g_c1[b * H1d + u] = c1n;
                g_h1[wp][b * H1d + u] = h1n;
            }
        }
        gbar(sense);

        // ---- P2: gates2 GEMM (32b x 32g permuted, K=192) + LSTM2 activation ----
        {
            float acc[2][2] = {};
            int tx = tid & 15, ty = tid >> 4, kk = tid & 31, lane8 = tid >> 5;
            for (int ch = 0; ch < 6; ch++) {
                int kg = ch * 32 + kk;
#pragma unroll
                for (int pp = 0; pp < 4; pp++) {
                    int bl = lane8 + pp * 8, b = b0p1 + bl;
                    float v = (kg < 128) ? __ldcg(&g_h1[wp][b * H1d + kg])
                                         : __ldcg(&g_h2[rp][b * H2d + (kg - 128)]);
                    su.p2.As[bl][kk] = v;
                }
#pragma unroll
                for (int pp = 0; pp < 4; pp++) {
                    int gl = lane8 + pp * 8;
                    su.p2.Ws[gl][kk] = g_W2p[(pg02 + gl) * 192 + kg];
                }
                __syncthreads();
#pragma unroll
                for (int k2 = 0; k2 < 32; k2++) {
                    float a0 = su.p2.As[ty * 2][k2], a1 = su.p2.As[ty * 2 + 1][k2];
                    float w0 = su.p2.Ws[tx * 2][k2], w1 = su.p2.Ws[tx * 2 + 1][k2];
                    acc[0][0] += a0 * w0; acc[0][1] += a0 * w1;
                    acc[1][0] += a1 * w0; acc[1][1] += a1 * w1;
                }
                __syncthreads();
            }
#pragma unroll
            for (int i = 0; i < 2; i++)
#pragma unroll
                for (int j = 0; j < 2; j++)
                    su.p2.sg[ty * 2 + i][tx * 2 + j] = acc[i][j] + g_b2p[pg02 + tx * 2 + j];
            __syncthreads();
            {
                int bl = tid & 31, ul = tid >> 5;   // ul 0..7
                float gi = su.p2.sg[bl][4 * ul], gf = su.p2.sg[bl][4 * ul + 1];
                float gg = su.p2.sg[bl][4 * ul + 2], go = su.p2.sg[bl][4 * ul + 3];
                int b = b0p1 + bl, u = u02 + ul;
                float c2n = sigf(gf) * g_c2[b * H2d + u] + sigf(gi) * tanhf(gg);
                float h2n = sigf(go) * tanhf(c2n);
                g_c2[b * H2d + u] = c2n;
                g_h2[wp][b * H2d + u] = h2n;
                g_z[(b * Lsteps + t) * 128 + u] = h2n;
            }
        }
        gbar(sense);

        // ---- P3: q + attention + ctx (4 rows per CTA) ----
        {
            int r = tid >> 6, l = tid & 63;
            int b = b0p3 + r;
            su.p3.h2[r][l] = __ldcg(&g_h2[wp][b * H2d + l]);
            __syncthreads();
            float qa = bq[l];
#pragma unroll 8
            for (int u = 0; u < 64; u++) qa += su.p3.h2[r][u] * g_WqT[u * 64 + l];
            su.p3.q[r][l] = qa;
            __syncthreads();

            // energy: thread handles 4 consecutive t = 4l..4l+3
            float4 e = {0.f, 0.f, 0.f, 0.f};
            const float* kb = g_keyT + (size_t)b * (Qd * Tlen) + 4 * l;
#pragma unroll 8
            for (int k = 0; k < 64; k++) {
                float qv = su.p3.q[r][k];
                float4 kv = *(const float4*)(kb + k * Tlen);
                e.x += qv * kv.x; e.y += qv * kv.y; e.z += qv * kv.z; e.w += qv * kv.w;
            }
            // max over 64-thread row group (2 warps)
            float mloc = fmaxf(fmaxf(e.x, e.y), fmaxf(e.z, e.w));
#pragma unroll
            for (int s = 16; s > 0; s >>= 1) mloc = fmaxf(mloc, __shfl_xor_sync(0xffffffffu, mloc, s));
            if ((tid & 31) == 0) su.p3.red[tid >> 5] = mloc;
            __syncthreads();
            float mx = fmaxf(su.p3.red[2 * r], su.p3.red[2 * r + 1]);
            float4 mk = *(const float4*)(mask + (size_t)b * Tlen + 4 * l);
            float w0 = expf(e.x - mx), w1 = expf(e.y - mx), w2 = expf(e.z - mx), w3 = expf(e.w - mx);
            float mw0 = mk.x * w0, mw1 = mk.y * w1, mw2 = mk.z * w2, mw3 = mk.w * w3;
            float s1 = w0 + w1 + w2 + w3, s2 = mw0 + mw1 + mw2 + mw3;
#pragma unroll
            for (int s = 16; s > 0; s >>= 1) {
                s1 += __shfl_xor_sync(0xffffffffu, s1, s);
                s2 += __shfl_xor_sync(0xffffffffu, s2, s);
            }
            if ((tid & 31) == 0) { su.p3.red[8 + (tid >> 5)] = s1; su.p3.red[16 + (tid >> 5)] = s2; }
            __syncthreads();
            float S1 = su.p3.red[8 + 2 * r] + su.p3.red[8 + 2 * r + 1];
            float S2 = su.p3.red[16 + 2 * r] + su.p3.red[16 + 2 * r + 1];
            float inv = 1.f / fmaxf(S2, 2e-30f * S1);
            float4 mav = {mw0 * inv, mw1 * inv, mw2 * inv, mw3 * inv};
            *(float4*)&su.p3.ma[r][4 * l] = mav;
            __syncthreads();

            // ctx: thread = (row rr, t-slice ts, v4) ; partial over 64 t's
            {
                int rr = tid >> 6, v4 = tid & 15, ts = (tid >> 4) & 3;
                int bb = b0p3 + rr;
                float4 a4 = {0.f, 0.f, 0.f, 0.f};
                const float* vb = values + (size_t)bb * Qd + 4 * v4;
#pragma unroll 4
                for (int tt2 = 0; tt2 < 64; tt2++) {
                    int tg = ts * 64 + tt2;
                    float m = su.p3.ma[rr][tg];
                    float4 vv = *(const float4*)(vb + (size_t)tg * (Bsz * Qd));
                    a4.x += m * vv.x; a4.y += m * vv.y; a4.z += m * vv.z; a4.w += m * vv.w;
                }
                *(float4*)&su.p3.ct[rr][ts][4 * v4] = a4;
            }
            __syncthreads();
            {
                int r2 = tid >> 6, v = tid & 63;
                float cx = su.p3.ct[r2][0][v] + su.p3.ct[r2][1][v] +
                           su.p3.ct[r2][2][v] + su.p3.ct[r2][3][v];
                int b2 = b0p3 + r2;
                g_ctx[b2 * Qd + v] = cx;
                g_z[(b2 * Lsteps + t) * 128 + 64 + v] = cx;
            }
        }
        gbar(sense);
    }
}

// ---------------- K4: final GEMM out[b][t][v] = z . W_out^T + b_out ----------------
__global__ void k_out(const float* __restrict__ Wout, const float* __restrict__ bout,
                      float* __restrict__ out) {
    __shared__ float As[64][65];
    __shared__ float Bs[64][65];
    int n0 = blockIdx.x * 64, m0 = blockIdx.y * 64;
    int tid = threadIdx.x;
    int tx = tid & 15, ty = tid >> 4;
    float acc[4][4] = {};
    int kk = tid & 63, rl4 = tid >> 6;

    for (int kc = 0; kc < 2; kc++) {
#pragma unroll
        for (int pp = 0; pp < 16; pp++) {
            int rl = rl4 + pp * 4;
            As[rl][kk] = g_z[(m0 + rl) * 128 + kc * 64 + kk];
            int col = n0 + rl;
            Bs[rl][kk] = (col < VOC) ? Wout[col * 128 + kc * 64 + kk] : 0.f;
        }
        __syncthreads();
#pragma unroll
        for (int k2 = 0; k2 < 64; k2++) {
            float a[4], bb[4];
#pragma unroll
            for (int i = 0; i < 4; i++) a[i] = As[i * 16 + ty][k2];
#pragma unroll
            for (int j = 0; j < 4; j++) bb[j] = Bs[j * 16 + tx][k2];
#pragma unroll
            for (int i = 0; i < 4; i++)
#pragma unroll
                for (int j = 0; j < 4; j++)
                    acc[i][j] += a[i] * bb[j];
        }
        __syncthreads();
    }
#pragma unroll
    for (int j = 0; j < 4; j++) {
        int col = n0 + j * 16 + tx;
        if (col < VOC) {
            float bo = bout[col];
#pragma unroll
            for (int i = 0; i < 4; i++) {
                int row = m0 + i * 16 + ty;
                out[(size_t)row * VOC + col] = acc[i][j] + bo;
            }
        }
    }
}

// ---------------- launcher ----------------
extern "C" void kernel_launch(void* const* d_in, const int* in_sizes, int n_in,
                              void* d_out, int out_size) {
    const float* key    = (const float*)d_in[0];
    const float* values = (const float*)d_in[1];
    const float* mask   = (const float*)d_in[2];
    const int*   text   = (const int*)d_in[3];
    const float* emb    = (const float*)d_in[4];
    const float* Wih1   = (const float*)d_in[5];
    const float* Whh1   = (const float*)d_in[6];
    const float* bih1   = (const float*)d_in[7];
    const float* bhh1   = (const float*)d_in[8];
    const float* Wih2   = (const float*)d_in[9];
    const float* Whh2   = (const float*)d_in[10];
    const float* bih2   = (const float*)d_in[11];
    const float* bhh2   = (const float*)d_in[12];
    const float* Wq     = (const float*)d_in[13];
    const float* bq     = (const float*)d_in[14];
    const float* Wout   = (const float*)d_in[15];
    const float* bout   = (const float*)d_in[16];
    float* out = (float*)d_out;

    k_recur<<<NCTA, 256>>>(key, values, mask, text, emb,
                           Wih1, Whh1, bih1, bhh1,
                           Wih2, Whh2, bih2, bhh2, Wq, bq);
    k_out<<<dim3(79, 232), 256>>>(Wout, bout, out);
}

// round 13
// speedup vs baseline: 2.1850x; 2.1176x over previous
#include <cuda_runtime.h>
#include <cuda_bf16.h>
#include <math.h>
#include <stdint.h>

#define Bsz 512
#define Tlen 256
#define Qd 64
#define EMBd 128
#define H1d 128
#define H2d 64
#define VOC 5000
#define VPAD 5120
#define Lsteps 29
#define LTEXT 30
#define NROW (Bsz * Lsteps)   /* 14848 */
#define NCTA_R 128
#define KP 136                /* padded K (bf16 elems) for ldmatrix bank spread */

// ---------------- persistent device scratch ----------------
__device__ float g_keyT[Bsz * Qd * Tlen];       // [b][k][t]
__device__ float g_W1T[192 * 512];              // [k][pg] fp32 (ctx|h1 weights, permuted gates)
__device__ float g_W2T[192 * 256];              // [k][pg]
__device__ float g_b1p[512];
__device__ float g_b2p[256];
__device__ float g_WqT[64 * 64];                // [u][j]
__device__ float g_G1e[(size_t)NROW * 512];     // emb contribution to gates1 (+bias)
__device__ __nv_bfloat16 g_zEh[(size_t)NROW * 128];
__device__ __nv_bfloat16 g_zEl[(size_t)NROW * 128];
__device__ __nv_bfloat16 g_W1eh[512 * 128];
__device__ __nv_bfloat16 g_W1el[512 * 128];
__device__ __nv_bfloat16 g_zh[(size_t)NROW * 128];
__device__ __nv_bfloat16 g_zl[(size_t)NROW * 128];
__device__ __nv_bfloat16 g_Woh[(size_t)VPAD * 128];
__device__ __nv_bfloat16 g_Wol[(size_t)VPAD * 128];
__device__ float g_boutp[VPAD];

__device__ __forceinline__ float sigf(float x) { return 1.f / (1.f + expf(-x)); }

__device__ __forceinline__ uint32_t s2u(const void* p) {
    uint32_t a;
    asm("{ .reg .u64 t; cvta.to.shared.u64 t, %1; cvt.u32.u64 %0, t; }" : "=r"(a) : "l"(p));
    return a;
}

// ================= prep: permute/split weights =================
__global__ void k_prep(const float* __restrict__ Wih1, const float* __restrict__ Whh1,
                       const float* __restrict__ bih1, const float* __restrict__ bhh1,
                       const float* __restrict__ Wih2, const float* __restrict__ Whh2,
                       const float* __restrict__ bih2, const float* __restrict__ bhh2,
                       const float* __restrict__ Wq, const float* __restrict__ Wout,
                       const float* __restrict__ bout) {
    int gid = blockIdx.x * blockDim.x + threadIdx.x;
    int stride = gridDim.x * blockDim.x;
    // W1T: [k 0..191][pg]  k<64 -> ctx weights (Wih1 cols 128..191), else h1 (Whh1)
    for (int i = gid; i < 192 * 512; i += stride) {
        int k = i >> 9, pg = i & 511;
        int u = pg >> 2, q = pg & 3, orow = q * 128 + u;
        g_W1T[i] = (k < 64) ? Wih1[orow * 192 + 128 + k] : Whh1[orow * 128 + (k - 64)];
    }
    // W1e split (emb part, for G1e GEMM): rows = permuted gate
    for (int i = gid; i < 512 * 128; i += stride) {
        int pg = i >> 7, kk = i & 127;
        int u = pg >> 2, q = pg & 3, orow = q * 128 + u;
        float v = Wih1[orow * 192 + kk];
        __nv_bfloat16 h = __float2bfloat16(v);
        g_W1eh[i] = h;
        g_W1el[i] = __float2bfloat16(v - __bfloat162float(h));
    }
    for (int i = gid; i < 512; i += stride) {
        int u = i >> 2, q = i & 3, orow = q * 128 + u;
        g_b1p[i] = bih1[orow] + bhh1[orow];
    }
    for (int i = gid; i < 192 * 256; i += stride) {
        int k = i >> 8, pg = i & 255;
        int u = pg >> 2, q = pg & 3, orow = q * 64 + u;
        g_W2T[i] = (k < 128) ? Wih2[orow * 128 + k] : Whh2[orow * 64 + (k - 128)];
    }
    for (int i = gid; i < 256; i += stride) {
        int u = i >> 2, q = i & 3, orow = q * 64 + u;
        g_b2p[i] = bih2[orow] + bhh2[orow];
    }
    for (int i = gid; i < 64 * 64; i += stride) {
        int u = i >> 6, j = i & 63;
        g_WqT[i] = Wq[j * 64 + u];
    }
    for (int i = gid; i < VPAD * 128; i += stride) {
        int v = i >> 7, kk = i & 127;
        float val = (v < VOC) ? Wout[v * 128 + kk] : 0.f;
        __nv_bfloat16 h = __float2bfloat16(val);
        g_Woh[i] = h;
        g_Wol[i] = __float2bfloat16(val - __bfloat162float(h));
    }
    for (int i = gid; i < VPAD; i += stride)
        g_boutp[i] = (i < VOC) ? bout[i] : 0.f;
}

// ================= gather emb rows + bf16 split =================
__global__ void k_gather(const int* __restrict__ text, const float* __restrict__ emb) {
    int gid = blockIdx.x * blockDim.x + threadIdx.x;
    int stride = gridDim.x * blockDim.x;
    for (int i = gid; i < NROW * 128; i += stride) {
        int r = i >> 7, c = i & 127;
        int b = r / Lsteps, t = r - b * Lsteps;
        int tok = text[b * LTEXT + t];
        float v = emb[tok * EMBd + c];
        __nv_bfloat16 h = __float2bfloat16(v);
        g_zEh[i] = h;
        g_zEl[i] = __float2bfloat16(v - __bfloat162float(h));
    }
}

// ================= key transpose =================
__global__ void k_keyT(const float* __restrict__ key) {
    __shared__ float s[64][65];
    int b = blockIdx.y, t0 = blockIdx.x * 64;
    int tid = threadIdx.x;
    int c = tid & 63, r4 = tid >> 6;
#pragma unroll
    for (int pp = 0; pp < 16; pp++) {
        int tl = r4 + pp * 4;
        s[tl][c] = key[((t0 + tl) * Bsz + b) * Qd + c];
    }
    __syncthreads();
#pragma unroll
    for (int pp = 0; pp < 16; pp++) {
        int kl = r4 + pp * 4;
        g_keyT[(b * Qd + kl) * Tlen + t0 + c] = s[c][kl];
    }
}

// ================= mma.sync bf16 GEMM: C = A @ B^T + bias (hi/lo split, 3 passes) =================
__device__ __forceinline__ void mma_bf16(float* d, const uint32_t* a, uint32_t b0, uint32_t b1) {
    asm volatile(
        "mma.sync.aligned.m16n8k16.row.col.f32.bf16.bf16.f32 "
        "{%0,%1,%2,%3}, {%4,%5,%6,%7}, {%8,%9}, {%0,%1,%2,%3};"
        : "+f"(d[0]), "+f"(d[1]), "+f"(d[2]), "+f"(d[3])
        : "r"(a[0]), "r"(a[1]), "r"(a[2]), "r"(a[3]), "r"(b0), "r"(b1));
}

__device__ __forceinline__ void gemm_pass(const __nv_bfloat16* sA, const __nv_bfloat16* sB,
                                          float acc[2][8][4], int lane, int wm0, int wn0) {
#pragma unroll
    for (int ks = 0; ks < 8; ks++) {
        int k0 = ks * 16;
        uint32_t af[2][4];
#pragma unroll
        for (int mi = 0; mi < 2; mi++) {
            uint32_t ad = s2u(&sA[(wm0 + mi * 16 + (lane & 15)) * KP + k0 + (lane >> 4) * 8]);
            asm volatile("ldmatrix.sync.aligned.m8n8.x4.shared.b16 {%0,%1,%2,%3}, [%4];"
                : "=r"(af[mi][0]), "=r"(af[mi][1]), "=r"(af[mi][2]), "=r"(af[mi][3]) : "r"(ad));
        }
#pragma unroll
        for (int nt = 0; nt < 4; nt++) {
            uint32_t bfr[4];
            uint32_t bd = s2u(&sB[(wn0 + nt * 16 + (lane & 15)) * KP + k0 + (lane >> 4) * 8]);
            asm volatile("ldmatrix.sync.aligned.m8n8.x4.shared.b16 {%0,%1,%2,%3}, [%4];"
                : "=r"(bfr[0]), "=r"(bfr[1]), "=r"(bfr[2]), "=r"(bfr[3]) : "r"(bd));
#pragma unroll
            for (int mi = 0; mi < 2; mi++) {
                mma_bf16(acc[mi][2 * nt],     af[mi], bfr[0], bfr[2]);
                mma_bf16(acc[mi][2 * nt + 1], af[mi], bfr[1], bfr[3]);
            }
        }
    }
}

__device__ __forceinline__ void load_tile(__nv_bfloat16* dst, const __nv_bfloat16* src,
                                          int row0, int tid) {
    for (int i = tid; i < 2048; i += 256) {
        int r = i >> 4, cq = (i & 15) * 8;
        *(uint4*)&dst[r * KP + cq] = *(const uint4*)&src[(size_t)(row0 + r) * 128 + cq];
    }
}

// smem: sA (Ah then Al) | sBh | sBl | bias  =  3*34816 + 512 = 104960 B
__global__ void __launch_bounds__(256, 2)
k_gemm_mma(const __nv_bfloat16* __restrict__ Ah, const __nv_bfloat16* __restrict__ Al,
           const __nv_bfloat16* __restrict__ Bh, const __nv_bfloat16* __restrict__ Bl,
           const float* __restrict__ bias, float* __restrict__ C, int Ncols, int ldC) {
    extern __shared__ char smg[];
    __nv_bfloat16* sA  = (__nv_bfloat16*)smg;
    __nv_bfloat16* sBh = (__nv_bfloat16*)(smg + 34816);
    __nv_bfloat16* sBl = (__nv_bfloat16*)(smg + 69632);
    float* sbias = (float*)(smg + 104448);
    int tid = threadIdx.x, lane = tid & 31, wid = tid >> 5;
    int n0 = blockIdx.x * 128, m0 = blockIdx.y * 128;
    int wm0 = (wid & 3) * 32, wn0 = (wid >> 2) * 64;

    load_tile(sA, Ah, m0, tid);
    load_tile(sBh, Bh, n0, tid);
    load_tile(sBl, Bl, n0, tid);
    if (tid < 128) sbias[tid] = bias[n0 + tid];
    __syncthreads();

    float acc[2][8][4];
#pragma unroll
    for (int i = 0; i < 2; i++)
#pragma unroll
        for (int j = 0; j < 8; j++)
#pragma unroll
            for (int k = 0; k < 4; k++) acc[i][j][k] = 0.f;

    gemm_pass(sA, sBh, acc, lane, wm0, wn0);   // hh
    gemm_pass(sA, sBl, acc, lane, wm0, wn0);   // hl
    __syncthreads();
    load_tile(sA, Al, m0, tid);                // Al overwrites Ah
    __syncthreads();
    gemm_pass(sA, sBh, acc, lane, wm0, wn0);   // lh

    // store: c0,c1 at (row, col..col+1); c2,c3 at (row+8, ...)
#pragma unroll
    for (int mi = 0; mi < 2; mi++) {
        int row = m0 + wm0 + mi * 16 + (lane >> 2);
#pragma unroll
        for (int nj = 0; nj < 8; nj++) {
            int lcol = wn0 + nj * 8 + (lane & 3) * 2;
            int col = n0 + lcol;
            if (col < Ncols) {
                float b0 = sbias[lcol], b1 = sbias[lcol + 1];
                float2 v0 = {acc[mi][nj][0] + b0, acc[mi][nj][1] + b1};
                float2 v1 = {acc[mi][nj][2] + b0, acc[mi][nj][3] + b1};
                *(float2*)&C[(size_t)row * ldC + col] = v0;
                *(float2*)&C[(size_t)(row + 8) * ldC + col] = v1;
            }
        }
    }
}

// ================= recurrence: 1 CTA = 4 batch rows, all 29 steps, no grid sync =================
// dynamic smem layout (float offsets):
#define SO_W2   0
#define SO_X1   49152
#define SO_X2   49920
#define SO_U    50688   // union: sg1[2048] | { ma[1024], ct[1024] }
#define SO_SG2  52736
#define SO_H2   53760
#define SO_Q    54016
#define SO_C1   54272
#define SO_C2   54784
#define SO_RED  55040
#define SO_B2   55072
#define R_SMEM_FLOATS 55328

__global__ void __launch_bounds__(256, 1)
k_recur2(const float* __restrict__ values, const float* __restrict__ mask,
         const float* __restrict__ bq) {
    extern __shared__ float s[];
    float* sW2  = s + SO_W2;        // [192][256]
    float* sx1  = s + SO_X1;        // [4][192] = [ctx | h1]
    float* sx2  = s + SO_X2;        // [4][192] = [h1new | h2old]
    float* ssg1 = s + SO_U;         // [4][512]
    float* sma  = s + SO_U;         // [4][256]
    float* sct  = s + SO_U + 1024;  // [4][4][64]
    float* ssg2 = s + SO_SG2;       // [4][256]
    float* sh2  = s + SO_H2;        // [4][64]
    float* sq   = s + SO_Q;         // [4][64]
    float* sc1  = s + SO_C1;        // [4][128]
    float* sc2  = s + SO_C2;        // [4][64]
    float* sred = s + SO_RED;       // [32]
    float* sb2  = s + SO_B2;        // [256]

    int tid = threadIdx.x;
    int b0 = blockIdx.x * 4;

    // CTA prologue: weights + state init
    for (int i = tid; i < 192 * 256; i += 256) sW2[i] = g_W2T[i];
    sb2[tid] = g_b2p[tid];
    for (int i = tid; i < 768; i += 256) { sx1[i] = 0.f; sx2[i] = 0.f; }
    for (int i = tid; i < 512; i += 256) sc1[i] = 0.f;
    for (int i = tid; i < 256; i += 256) { sc2[i] = 0.f; sh2[i] = 0.f; }
    __syncthreads();

    for (int t = 0; t < Lsteps; t++) {
        // ---- P1: gates1 = x1 @ W1T + G1e (emb part precomputed, bias folded) ----
        {
            int pg = tid * 2;
            float2 acc[4];
#pragma unroll
            for (int r = 0; r < 4; r++)
                acc[r] = *(const float2*)&g_G1e[((size_t)(b0 + r) * Lsteps + t) * 512 + pg];
#pragma unroll 4
            for (int k = 0; k < 192; k += 4) {
                float4 a[4];
#pragma unroll
                for (int r = 0; r < 4; r++) a[r] = *(const float4*)&sx1[r * 192 + k];
#pragma unroll
                for (int kk = 0; kk < 4; kk++) {
                    float2 w = *(const float2*)&g_W1T[(k + kk) * 512 + pg];
                    float av0 = (kk == 0) ? a[0].x : (kk == 1) ? a[0].y : (kk == 2) ? a[0].z : a[0].w;
                    float av1 = (kk == 0) ? a[1].x : (kk == 1) ? a[1].y : (kk == 2) ? a[1].z : a[1].w;
                    float av2 = (kk == 0) ? a[2].x : (kk == 1) ? a[2].y : (kk == 2) ? a[2].z : a[2].w;
                    float av3 = (kk == 0) ? a[3].x : (kk == 1) ? a[3].y : (kk == 2) ? a[3].z : a[3].w;
                    acc[0].x += av0 * w.x; acc[0].y += av0 * w.y;
                    acc[1].x += av1 * w.x; acc[1].y += av1 * w.y;
                    acc[2].x += av2 * w.x; acc[2].y += av2 * w.y;
                    acc[3].x += av3 * w.x; acc[3].y += av3 * w.y;
                }
            }
#pragma unroll
            for (int r = 0; r < 4; r++) {
                ssg1[r * 512 + pg] = acc[r].x;
                ssg1[r * 512 + pg + 1] = acc[r].y;
            }
        }
        __syncthreads();
        // ---- LSTM1 activation ----
#pragma unroll
        for (int i = 0; i < 2; i++) {
            int idx = tid + 256 * i;
            int r = idx >> 7, u = idx & 127;
            float4 g = *(float4*)&ssg1[r * 512 + 4 * u];
            float c = sigf(g.y) * sc1[r * 128 + u] + sigf(g.x) * tanhf(g.z);
            float h = sigf(g.w) * tanhf(c);
            sc1[r * 128 + u] = c;
            sx2[r * 192 + u] = h;
            sx1[r * 192 + 64 + u] = h;
        }
        __syncthreads();
        // ---- P2: gates2 = x2 @ W2T (SMEM-resident weights) ----
        {
            float acc2[4];
#pragma unroll
            for (int r = 0; r < 4; r++) acc2[r] = sb2[tid];
#pragma unroll 4
            for (int k = 0; k < 192; k += 4) {
                float4 a[4];
#pragma unroll
                for (int r = 0; r < 4; r++) a[r] = *(const float4*)&sx2[r * 192 + k];
#pragma unroll
                for (int kk = 0; kk < 4; kk++) {
                    float w = sW2[(k + kk) * 256 + tid];
                    float av0 = (kk == 0) ? a[0].x : (kk == 1) ? a[0].y : (kk == 2) ? a[0].z : a[0].w;
                    float av1 = (kk == 0) ? a[1].x : (kk == 1) ? a[1].y : (kk == 2) ? a[1].z : a[1].w;
                    float av2 = (kk == 0) ? a[2].x : (kk == 1) ? a[2].y : (kk == 2) ? a[2].z : a[2].w;
                    float av3 = (kk == 0) ? a[3].x : (kk == 1) ? a[3].y : (kk == 2) ? a[3].z : a[3].w;
                    acc2[0] += av0 * w; acc2[1] += av1 * w;
                    acc2[2] += av2 * w; acc2[3] += av3 * w;
                }
            }
#pragma unroll
            for (int r = 0; r < 4; r++) ssg2[r * 256 + tid] = acc2[r];
        }
        __syncthreads();
        // ---- LSTM2 activation + z(h2) write ----
        {
            int r = tid >> 6, u = tid & 63;
            float4 g = *(float4*)&ssg2[r * 256 + 4 * u];
            float c = sigf(g.y) * sc2[r * 64 + u] + sigf(g.x) * tanhf(g.z);
            float h = sigf(g.w) * tanhf(c);
            sc2[r * 64 + u] = c;
            sh2[r * 64 + u] = h;
            sx2[r * 192 + 128 + u] = h;   // h2 for next step's P2
            size_t row = (size_t)(b0 + r) * Lsteps + t;
            __nv_bfloat16 hh = __float2bfloat16(h);
            g_zh[row * 128 + u] = hh;
            g_zl[row * 128 + u] = __float2bfloat16(h - __bfloat162float(hh));
        }
        __syncthreads();
        // ---- q projection ----
        {
            int r = tid >> 6, j = tid & 63;
            float qa = __ldg(&bq[j]);
#pragma unroll 8
            for (int u = 0; u < 64; u++)
                qa += sh2[r * 64 + u] * __ldg(&g_WqT[u * 64 + j]);
            sq[r * 64 + j] = qa;
        }
        __syncthreads();
        // ---- attention: energy + softmax ----
        {
            int r = tid >> 6, l = tid & 63;
            int b = b0 + r;
            float4 e = {0.f, 0.f, 0.f, 0.f};
            const float* kb = g_keyT + (size_t)b * (Qd * Tlen) + 4 * l;
#pragma unroll 8
            for (int k = 0; k < 64; k++) {
                float qv = sq[r * 64 + k];
                float4 kv = *(const float4*)(kb + k * Tlen);
                e.x += qv * kv.x; e.y += qv * kv.y; e.z += qv * kv.z; e.w += qv * kv.w;
            }
            float mloc = fmaxf(fmaxf(e.x, e.y), fmaxf(e.z, e.w));
#pragma unroll
            for (int sh = 16; sh > 0; sh >>= 1)
                mloc = fmaxf(mloc, __shfl_xor_sync(0xffffffffu, mloc, sh));
            if ((tid & 31) == 0) sred[tid >> 5] = mloc;
            __syncthreads();
            float mx = fmaxf(sred[2 * r], sred[2 * r + 1]);
            float4 mk = *(const float4*)(mask + (size_t)b * Tlen + 4 * l);
            float w0 = expf(e.x - mx), w1 = expf(e.y - mx), w2 = expf(e.z - mx), w3 = expf(e.w - mx);
            float mw0 = mk.x * w0, mw1 = mk.y * w1, mw2 = mk.z * w2, mw3 = mk.w * w3;
            float s1 = w0 + w1 + w2 + w3, s2 = mw0 + mw1 + mw2 + mw3;
#pragma unroll
            for (int sh = 16; sh > 0; sh >>= 1) {
                s1 += __shfl_xor_sync(0xffffffffu, s1, sh);
                s2 += __shfl_xor_sync(0xffffffffu, s2, sh);
            }
            if ((tid & 31) == 0) { sred[8 + (tid >> 5)] = s1; sred[16 + (tid >> 5)] = s2; }
            __syncthreads();
            float S1 = sred[8 + 2 * r] + sred[8 + 2 * r + 1];
            float S2 = sred[16 + 2 * r] + sred[16 + 2 * r + 1];
            float inv = 1.f / fmaxf(S2, 2e-30f * S1);
            float4 mav = {mw0 * inv, mw1 * inv, mw2 * inv, mw3 * inv};
            *(float4*)&sma[r * 256 + 4 * l] = mav;
        }
        __syncthreads();
        // ---- ctx = ma @ values ----
        {
            int rr = tid >> 6, v4 = tid & 15, ts = (tid >> 4) & 3;
            int bb = b0 + rr;
            float4 a4 = {0.f, 0.f, 0.f, 0.f};
            const float* vb = values + (size_t)bb * Qd + 4 * v4;
#pragma unroll 4
            for (int tt = 0; tt < 64; tt++) {
                int tg = ts * 64 + tt;
                float m = sma[rr * 256 + tg];
                float4 vv = *(const float4*)(vb + (size_t)tg * (Bsz * Qd));
                a4.x += m * vv.x; a4.y += m * vv.y; a4.z += m * vv.z; a4.w += m * vv.w;
            }
            *(float4*)&sct[(rr * 4 + ts) * 64 + 4 * v4] = a4;
        }
        __syncthreads();
        {
            int r2 = tid >> 6, v = tid & 63;
            float cx = sct[(r2 * 4 + 0) * 64 + v] + sct[(r2 * 4 + 1) * 64 + v] +
                       sct[(r2 * 4 + 2) * 64 + v] + sct[(r2 * 4 + 3) * 64 + v];
            sx1[r2 * 192 + v] = cx;    // ctx for next step's P1
            size_t row = (size_t)(b0 + r2) * Lsteps + t;
            __nv_bfloat16 ch = __float2bfloat16(cx);
            g_zh[row * 128 + 64 + v] = ch;
            g_zl[row * 128 + 64 + v] = __float2bfloat16(cx - __bfloat162float(ch));
        }
        __syncthreads();
    }
}

// ================= launcher =================
extern "C" void kernel_launch(void* const* d_in, const int* in_sizes, int n_in,
                              void* d_out, int out_size) {
    const float* key    = (const float*)d_in[0];
    const float* values = (const float*)d_in[1];
    const float* mask   = (const float*)d_in[2];
    const int*   text   = (const int*)d_in[3];
    const float* emb    = (const float*)d_in[4];
    const float* Wih1   = (const float*)d_in[5];
    const float* Whh1   = (const float*)d_in[6];
    const float* bih1   = (const float*)d_in[7];
    const float* bhh1   = (const float*)d_in[8];
    const float* Wih2   = (const float*)d_in[9];
    const float* Whh2   = (const float*)d_in[10];
    const float* bih2   = (const float*)d_in[11];
    const float* bhh2   = (const float*)d_in[12];
    const float* Wq     = (const float*)d_in[13];
    const float* bq     = (const float*)d_in[14];
    const float* Wout   = (const float*)d_in[15];
    const float* bout   = (const float*)d_in[16];
    float* out = (float*)d_out;

    // symbol addresses (address queries only; no allocation)
    void *p_zEh, *p_zEl, *p_W1eh, *p_W1el, *p_b1p, *p_G1e;
    void *p_zh, *p_zl, *p_Woh, *p_Wol, *p_boutp;
    cudaGetSymbolAddress(&p_zEh, g_zEh);
    cudaGetSymbolAddress(&p_zEl, g_zEl);
    cudaGetSymbolAddress(&p_W1eh, g_W1eh);
    cudaGetSymbolAddress(&p_W1el, g_W1el);
    cudaGetSymbolAddress(&p_b1p, g_b1p);
    cudaGetSymbolAddress(&p_G1e, g_G1e);
    cudaGetSymbolAddress(&p_zh, g_zh);
    cudaGetSymbolAddress(&p_zl, g_zl);
    cudaGetSymbolAddress(&p_Woh, g_Woh);
    cudaGetSymbolAddress(&p_Wol, g_Wol);
    cudaGetSymbolAddress(&p_boutp, g_boutp);

    cudaFuncSetAttribute(k_gemm_mma, cudaFuncAttributeMaxDynamicSharedMemorySize, 104960);
    cudaFuncSetAttribute(k_recur2, cudaFuncAttributeMaxDynamicSharedMemorySize,
                         R_SMEM_FLOATS * 4);

    k_prep<<<256, 256>>>(Wih1, Whh1, bih1, bhh1, Wih2, Whh2, bih2, bhh2, Wq, Wout, bout);
    k_gather<<<256, 256>>>(text, emb);
    k_keyT<<<dim3(4, Bsz), 256>>>(key);

    // G1e = zE @ W1e^T + b1p   (M=14848, N=512, K=128)
    k_gemm_mma<<<dim3(512 / 128, NROW / 128), 256, 104960>>>(
        (const __nv_bfloat16*)p_zEh, (const __nv_bfloat16*)p_zEl,
        (const __nv_bfloat16*)p_W1eh, (const __nv_bfloat16*)p_W1el,
        (const float*)p_b1p, (float*)p_G1e, 512, 512);

    k_recur2<<<NCTA_R, 256, R_SMEM_FLOATS * 4>>>(values, mask, bq);

    // out = z @ Wout^T + bout  (M=14848, N=5000 padded 5120, K=128)
    k_gemm_mma<<<dim3(VPAD / 128, NROW / 128), 256, 104960>>>(
        (const __nv_bfloat16*)p_zh, (const __nv_bfloat16*)p_zl,
        (const __nv_bfloat16*)p_Woh, (const __nv_bfloat16*)p_Wol,
        (const float*)p_boutp, out, VOC, VOC);
}

// round 17
// speedup vs baseline: 2.2853x; 1.0459x over previous
#include <cuda_runtime.h>
#include <cuda_bf16.h>
#include <math.h>
#include <stdint.h>

#define Bsz 512
#define Tlen 256
#define Qd 64
#define EMBd 128
#define H1d 128
#define H2d 64
#define VOC 5000
#define VPAD 5120
#define Lsteps 29
#define LTEXT 30
#define NROW (Bsz * Lsteps)   /* 14848 */
#define NCTA_R 128
#define KP 136                /* padded K (bf16 elems) for ldmatrix bank spread */

// ---------------- persistent device scratch ----------------
__device__ float g_keyT[Bsz * Qd * Tlen];       // [b][k][t]
__device__ float g_W1T[192 * 512];              // k-pair packed: [(k>>1)][pg][k&1]
__device__ float g_W2T[192 * 256];              // k-pair packed
__device__ float g_b1p[512];
__device__ float g_b2p[256];
__device__ float g_WqT[64 * 64];                // [u][j]
__device__ float g_G1e[(size_t)NROW * 512];     // emb contribution to gates1 (+bias)
__device__ __nv_bfloat16 g_zEh[(size_t)NROW * 128];
__device__ __nv_bfloat16 g_zEl[(size_t)NROW * 128];
__device__ __nv_bfloat16 g_W1eh[512 * 128];
__device__ __nv_bfloat16 g_W1el[512 * 128];
__device__ __nv_bfloat16 g_zh[(size_t)NROW * 128];
__device__ __nv_bfloat16 g_zl[(size_t)NROW * 128];
__device__ __nv_bfloat16 g_Woh[(size_t)VPAD * 128];
__device__ __nv_bfloat16 g_Wol[(size_t)VPAD * 128];
__device__ float g_boutp[VPAD];

__device__ __forceinline__ float tanha(float x) {
    float y;
    asm("tanh.approx.f32 %0, %1;" : "=f"(y) : "f"(x));
    return y;
}
__device__ __forceinline__ float sigt(float x) {
    return fmaf(tanha(0.5f * x), 0.5f, 0.5f);
}

__device__ __forceinline__ uint32_t s2u(const void* p) {
    uint32_t a;
    asm("{ .reg .u64 t; cvta.to.shared.u64 t, %1; cvt.u32.u64 %0, t; }" : "=r"(a) : "l"(p));
    return a;
}

// ================= prep: permute/split weights =================
__global__ void k_prep(const float* __restrict__ Wih1, const float* __restrict__ Whh1,
                       const float* __restrict__ bih1, const float* __restrict__ bhh1,
                       const float* __restrict__ Wih2, const float* __restrict__ Whh2,
                       const float* __restrict__ bih2, const float* __restrict__ bhh2,
                       const float* __restrict__ Wq, const float* __restrict__ Wout,
                       const float* __restrict__ bout) {
    int gid = blockIdx.x * blockDim.x + threadIdx.x;
    int stride = gridDim.x * blockDim.x;
    // W1T (k-pair packed): k<64 -> ctx weights (Wih1 cols 128..191), else h1 (Whh1)
    for (int i = gid; i < 192 * 512; i += stride) {
        int k = i >> 9, pg = i & 511;
        int u = pg >> 2, q = pg & 3, orow = q * 128 + u;
        float v = (k < 64) ? Wih1[orow * 192 + 128 + k] : Whh1[orow * 128 + (k - 64)];
        g_W1T[(k >> 1) * 1024 + pg * 2 + (k & 1)] = v;
    }
    // W1e split (emb part, for G1e GEMM): rows = permuted gate
    for (int i = gid; i < 512 * 128; i += stride) {
        int pg = i >> 7, kk = i & 127;
        int u = pg >> 2, q = pg & 3, orow = q * 128 + u;
        float v = Wih1[orow * 192 + kk];
        __nv_bfloat16 h = __float2bfloat16(v);
        g_W1eh[i] = h;
        g_W1el[i] = __float2bfloat16(v - __bfloat162float(h));
    }
    for (int i = gid; i < 512; i += stride) {
        int u = i >> 2, q = i & 3, orow = q * 128 + u;
        g_b1p[i] = bih1[orow] + bhh1[orow];
    }
    for (int i = gid; i < 192 * 256; i += stride) {
        int k = i >> 8, pg = i & 255;
        int u = pg >> 2, q = pg & 3, orow = q * 64 + u;
        float v = (k < 128) ? Wih2[orow * 128 + k] : Whh2[orow * 64 + (k - 128)];
        g_W2T[(k >> 1) * 512 + pg * 2 + (k & 1)] = v;
    }
    for (int i = gid; i < 256; i += stride) {
        int u = i >> 2, q = i & 3, orow = q * 64 + u;
        g_b2p[i] = bih2[orow] + bhh2[orow];
    }
    for (int i = gid; i < 64 * 64; i += stride) {
        int u = i >> 6, j = i & 63;
        g_WqT[i] = Wq[j * 64 + u];
    }
    for (int i = gid; i < VPAD * 128; i += stride) {
        int v = i >> 7, kk = i & 127;
        float val = (v < VOC) ? Wout[v * 128 + kk] : 0.f;
        __nv_bfloat16 h = __float2bfloat16(val);
        g_Woh[i] = h;
        g_Wol[i] = __float2bfloat16(val - __bfloat162float(h));
    }
    for (int i = gid; i < VPAD; i += stride)
        g_boutp[i] = (i < VOC) ? bout[i] : 0.f;
}

// ================= gather emb rows + bf16 split =================
__global__ void k_gather(const int* __restrict__ text, const float* __restrict__ emb) {
    int gid = blockIdx.x * blockDim.x + threadIdx.x;
    int stride = gridDim.x * blockDim.x;
    for (int i = gid; i < NROW * 128; i += stride) {
        int r = i >> 7, c = i & 127;
        int b = r / Lsteps, t = r - b * Lsteps;
        int tok = text[b * LTEXT + t];
        float v = emb[tok * EMBd + c];
        __nv_bfloat16 h = __float2bfloat16(v);
        g_zEh[i] = h;
        g_zEl[i] = __float2bfloat16(v - __bfloat162float(h));
    }
}

// ================= key transpose =================
__global__ void k_keyT(const float* __restrict__ key) {
    __shared__ float s[64][65];
    int b = blockIdx.y, t0 = blockIdx.x * 64;
    int tid = threadIdx.x;
    int c = tid & 63, r4 = tid >> 6;
#pragma unroll
    for (int pp = 0; pp < 16; pp++) {
        int tl = r4 + pp * 4;
        s[tl][c] = key[((t0 + tl) * Bsz + b) * Qd + c];
    }
    __syncthreads();
#pragma unroll
    for (int pp = 0; pp < 16; pp++) {
        int kl = r4 + pp * 4;
        g_keyT[(b * Qd + kl) * Tlen + t0 + c] = s[c][kl];
    }
}

// ================= mma.sync bf16 GEMM: C = A @ B^T + bias (hi/lo split, 3 passes) =================
__device__ __forceinline__ void mma_bf16(float* d, const uint32_t* a, uint32_t b0, uint32_t b1) {
    asm volatile(
        "mma.sync.aligned.m16n8k16.row.col.f32.bf16.bf16.f32 "
        "{%0,%1,%2,%3}, {%4,%5,%6,%7}, {%8,%9}, {%0,%1,%2,%3};"
        : "+f"(d[0]), "+f"(d[1]), "+f"(d[2]), "+f"(d[3])
        : "r"(a[0]), "r"(a[1]), "r"(a[2]), "r"(a[3]), "r"(b0), "r"(b1));
}

__device__ __forceinline__ void gemm_pass(const __nv_bfloat16* sA, const __nv_bfloat16* sB,
                                          float acc[2][8][4], int lane, int wm0, int wn0) {
#pragma unroll
    for (int ks = 0; ks < 8; ks++) {
        int k0 = ks * 16;
        uint32_t af[2][4];
#pragma unroll
        for (int mi = 0; mi < 2; mi++) {
            uint32_t ad = s2u(&sA[(wm0 + mi * 16 + (lane & 15)) * KP + k0 + (lane >> 4) * 8]);
            asm volatile("ldmatrix.sync.aligned.m8n8.x4.shared.b16 {%0,%1,%2,%3}, [%4];"
                : "=r"(af[mi][0]), "=r"(af[mi][1]), "=r"(af[mi][2]), "=r"(af[mi][3]) : "r"(ad));
        }
#pragma unroll
        for (int nt = 0; nt < 4; nt++) {
            uint32_t bfr[4];
            uint32_t bd = s2u(&sB[(wn0 + nt * 16 + (lane & 15)) * KP + k0 + (lane >> 4) * 8]);
            asm volatile("ldmatrix.sync.aligned.m8n8.x4.shared.b16 {%0,%1,%2,%3}, [%4];"
                : "=r"(bfr[0]), "=r"(bfr[1]), "=r"(bfr[2]), "=r"(bfr[3]) : "r"(bd));
#pragma unroll
            for (int mi = 0; mi < 2; mi++) {
                mma_bf16(acc[mi][2 * nt],     af[mi], bfr[0], bfr[2]);
                mma_bf16(acc[mi][2 * nt + 1], af[mi], bfr[1], bfr[3]);
            }
        }
    }
}

__device__ __forceinline__ void load_tile(__nv_bfloat16* dst, const __nv_bfloat16* src,
                                          int row0, int tid) {
    for (int i = tid; i < 2048; i += 256) {
        int r = i >> 4, cq = (i & 15) * 8;
        *(uint4*)&dst[r * KP + cq] = *(const uint4*)&src[(size_t)(row0 + r) * 128 + cq];
    }
}

// smem: sA (Ah then Al) | sBh | sBl | bias  =  3*34816 + 512 = 104960 B
__global__ void __launch_bounds__(256, 2)
k_gemm_mma(const __nv_bfloat16* __restrict__ Ah, const __nv_bfloat16* __restrict__ Al,
           const __nv_bfloat16* __restrict__ Bh, const __nv_bfloat16* __restrict__ Bl,
           const float* __restrict__ bias, float* __restrict__ C, int Ncols, int ldC) {
    extern __shared__ char smg[];
    __nv_bfloat16* sA  = (__nv_bfloat16*)smg;
    __nv_bfloat16* sBh = (__nv_bfloat16*)(smg + 34816);
    __nv_bfloat16* sBl = (__nv_bfloat16*)(smg + 69632);
    float* sbias = (float*)(smg + 104448);
    int tid = threadIdx.x, lane = tid & 31, wid = tid >> 5;
    int n0 = blockIdx.x * 128, m0 = blockIdx.y * 128;
    int wm0 = (wid & 3) * 32, wn0 = (wid >> 2) * 64;

    load_tile(sA, Ah, m0, tid);
    load_tile(sBh, Bh, n0, tid);
    load_tile(sBl, Bl, n0, tid);
    if (tid < 128) sbias[tid] = bias[n0 + tid];
    __syncthreads();

    float acc[2][8][4];
#pragma unroll
    for (int i = 0; i < 2; i++)
#pragma unroll
        for (int j = 0; j < 8; j++)
#pragma unroll
            for (int k = 0; k < 4; k++) acc[i][j][k] = 0.f;

    gemm_pass(sA, sBh, acc, lane, wm0, wn0);   // hh
    gemm_pass(sA, sBl, acc, lane, wm0, wn0);   // hl
    __syncthreads();
    load_tile(sA, Al, m0, tid);                // Al overwrites Ah
    __syncthreads();
    gemm_pass(sA, sBh, acc, lane, wm0, wn0);   // lh

#pragma unroll
    for (int mi = 0; mi < 2; mi++) {
        int row = m0 + wm0 + mi * 16 + (lane >> 2);
#pragma unroll
        for (int nj = 0; nj < 8; nj++) {
            int lcol = wn0 + nj * 8 + (lane & 3) * 2;
            int col = n0 + lcol;
            if (col < Ncols) {
                float b0 = sbias[lcol], b1 = sbias[lcol + 1];
                float2 v0 = {acc[mi][nj][0] + b0, acc[mi][nj][1] + b1};
                float2 v1 = {acc[mi][nj][2] + b0, acc[mi][nj][3] + b1};
                *(float2*)&C[(size_t)row * ldC + col] = v0;
                *(float2*)&C[(size_t)(row + 8) * ldC + col] = v1;
            }
        }
    }
}

// ================= recurrence: 1 CTA = 4 batch rows, 512 threads, no grid sync =================
// dynamic smem layout (float offsets):
#define SO_W2   0
#define SO_X1   49152
#define SO_X2   49920
#define SO_U    50688            // union: ssg1[2048] | { sma[1024], sct[2048] }
#define SO_SG2  53760
#define SO_H2   54784
#define SO_Q    55040
#define SO_C1   55296
#define SO_C2   55808
#define SO_RED  56064
#define SO_B2   56128
#define R_SMEM_FLOATS 56384      /* 225536 bytes */

__global__ void __launch_bounds__(512, 1)
k_recur2(const float* __restrict__ values, const float* __restrict__ mask,
         const float* __restrict__ bq) {
    extern __shared__ float s[];
    float* sW2  = s + SO_W2;        // [96][256][2] k-pair packed
    float* sx1  = s + SO_X1;        // [4][192] = [ctx | h1]
    float* sx2  = s + SO_X2;        // [4][192] = [h1new | h2old]
    float* ssg1 = s + SO_U;         // [4][512]
    float* sma  = s + SO_U;         // [4][256]
    float* sct  = s + SO_U + 1024;  // [4][8][64]
    float* ssg2 = s + SO_SG2;       // [4][256]
    float* sh2  = s + SO_H2;        // [4][64]
    float* sq   = s + SO_Q;         // [4][64]
    float* sc1  = s + SO_C1;        // [4][128]
    float* sc2  = s + SO_C2;        // [4][64]
    float* sred = s + SO_RED;       // [64]
    float* sb2  = s + SO_B2;        // [256]

    int tid = threadIdx.x;
    int b0 = blockIdx.x * 4;

    // CTA prologue
    for (int i = tid; i < 192 * 256; i += 512) sW2[i] = g_W2T[i];
    if (tid < 256) sb2[tid] = g_b2p[tid];
    for (int i = tid; i < 768; i += 512) { sx1[i] = 0.f; sx2[i] = 0.f; }
    sc1[tid] = 0.f;
    if (tid < 256) sc2[tid] = 0.f;
    __syncthreads();

    for (int t = 0; t < Lsteps; t++) {
        // ---- P1: gates1 = x1 @ W1T + G1e (512 threads, 1 pg each) ----
        {
            int pg = tid;
            float acc[4];
#pragma unroll
            for (int r = 0; r < 4; r++)
                acc[r] = g_G1e[((size_t)(b0 + r) * Lsteps + t) * 512 + pg];
            const float2* W12 = (const float2*)g_W1T;
#pragma unroll 4
            for (int k2 = 0; k2 < 96; k2++) {
                float2 w = W12[k2 * 512 + pg];
#pragma unroll
                for (int r = 0; r < 4; r++) {
                    float2 x = *(const float2*)&sx1[r * 192 + 2 * k2];
                    acc[r] = fmaf(x.x, w.x, fmaf(x.y, w.y, acc[r]));
                }
            }
#pragma unroll
            for (int r = 0; r < 4; r++) ssg1[r * 512 + pg] = acc[r];
        }
        __syncthreads();
        // ---- LSTM1 activation (512 threads) ----
        {
            int r = tid >> 7, u = tid & 127;
            float4 g = *(float4*)&ssg1[r * 512 + 4 * u];
            float c = sigt(g.y) * sc1[r * 128 + u] + sigt(g.x) * tanha(g.z);
            float h = sigt(g.w) * tanha(c);
            sc1[r * 128 + u] = c;
            sx2[r * 192 + u] = h;
            sx1[r * 192 + 64 + u] = h;
        }
        __syncthreads();
        // ---- P2: gates2 = x2 @ W2T (SMEM, 256 threads) ----
        if (tid < 256) {
            int pg = tid;
            float acc2[4];
#pragma unroll
            for (int r = 0; r < 4; r++) acc2[r] = sb2[pg];
            const float2* W22 = (const float2*)sW2;
#pragma unroll 4
            for (int k2 = 0; k2 < 96; k2++) {
                float2 w = W22[k2 * 256 + pg];
#pragma unroll
                for (int r = 0; r < 4; r++) {
                    float2 x = *(const float2*)&sx2[r * 192 + 2 * k2];
                    acc2[r] = fmaf(x.x, w.x, fmaf(x.y, w.y, acc2[r]));
                }
            }
#pragma unroll
            for (int r = 0; r < 4; r++) ssg2[r * 256 + pg] = acc2[r];
        }
        __syncthreads();
        // ---- LSTM2 activation + z(h2) write (256 threads) ----
        if (tid < 256) {
            int r = tid >> 6, u = tid & 63;
            float4 g = *(float4*)&ssg2[r * 256 + 4 * u];
            float c = sigt(g.y) * sc2[r * 64 + u] + sigt(g.x) * tanha(g.z);
            float h = sigt(g.w) * tanha(c);
            sc2[r * 64 + u] = c;
            sh2[r * 64 + u] = h;
            sx2[r * 192 + 128 + u] = h;
            size_t row = (size_t)(b0 + r) * Lsteps + t;
            __nv_bfloat16 hh = __float2bfloat16(h);
            g_zh[row * 128 + u] = hh;
            g_zl[row * 128 + u] = __float2bfloat16(h - __bfloat162float(hh));
        }
        __syncthreads();
        // ---- q projection (256 threads) ----
        if (tid < 256) {
            int r = tid >> 6, j = tid & 63;
            float qa = __ldg(&bq[j]);
#pragma unroll 8
            for (int u = 0; u < 64; u++)
                qa = fmaf(sh2[r * 64 + u], __ldg(&g_WqT[u * 64 + j]), qa);
            sq[r * 64 + j] = qa;
        }
        __syncthreads();
        // ---- attention: energy + softmax (512 threads, 2 t each) ----
        {
            int r = tid >> 7, l = tid & 127;
            int b = b0 + r;
            float ex = 0.f, ey = 0.f;
            const float* kb = g_keyT + (size_t)b * (Qd * Tlen) + 2 * l;
#pragma unroll 8
            for (int k = 0; k < 64; k++) {
                float qv = sq[r * 64 + k];
                float2 kv = *(const float2*)(kb + k * Tlen);
                ex = fmaf(qv, kv.x, ex);
                ey = fmaf(qv, kv.y, ey);
            }
            float mloc = fmaxf(ex, ey);
#pragma unroll
            for (int sh = 16; sh > 0; sh >>= 1)
                mloc = fmaxf(mloc, __shfl_xor_sync(0xffffffffu, mloc, sh));
            int wid = tid >> 5;
            if ((tid & 31) == 0) sred[wid] = mloc;
            __syncthreads();
            float mx = fmaxf(fmaxf(sred[4 * r], sred[4 * r + 1]),
                             fmaxf(sred[4 * r + 2], sred[4 * r + 3]));
            float2 mk = *(const float2*)(mask + (size_t)b * Tlen + 2 * l);
            float w0 = __expf(ex - mx), w1 = __expf(ey - mx);
            float mw0 = mk.x * w0, mw1 = mk.y * w1;
            float s1 = w0 + w1, s2 = mw0 + mw1;
#pragma unroll
            for (int sh = 16; sh > 0; sh >>= 1) {
                s1 += __shfl_xor_sync(0xffffffffu, s1, sh);
                s2 += __shfl_xor_sync(0xffffffffu, s2, sh);
            }
            if ((tid & 31) == 0) { sred[16 + wid] = s1; sred[32 + wid] = s2; }
            __syncthreads();
            float S1 = sred[16 + 4 * r] + sred[16 + 4 * r + 1] +
                       sred[16 + 4 * r + 2] + sred[16 + 4 * r + 3];
            float S2 = sred[32 + 4 * r] + sred[32 + 4 * r + 1] +
                       sred[32 + 4 * r + 2] + sred[32 + 4 * r + 3];
            float inv = 1.f / fmaxf(S2, 2e-30f * S1);
            float2 mav = {mw0 * inv, mw1 * inv};
            *(float2*)&sma[r * 256 + 2 * l] = mav;
        }
        __syncthreads();
        // ---- ctx = ma @ values (512 threads: 4 rows x 8 t-slices x 16 v4) ----
        {
            int rr = tid >> 7, v4 = tid & 15, ts = (tid >> 4) & 7;
            int bb = b0 + rr;
            float4 a4 = {0.f, 0.f, 0.f, 0.f};
            const float* vb = values + (size_t)bb * Qd + 4 * v4;
#pragma unroll 4
            for (int tt = 0; tt < 32; tt++) {
                int tg = ts * 32 + tt;
                float m = sma[rr * 256 + tg];
                float4 vv = *(const float4*)(vb + (size_t)tg * (Bsz * Qd));
                a4.x = fmaf(m, vv.x, a4.x);
                a4.y = fmaf(m, vv.y, a4.y);
                a4.z = fmaf(m, vv.z, a4.z);
                a4.w = fmaf(m, vv.w, a4.w);
            }
            *(float4*)&sct[(rr * 8 + ts) * 64 + 4 * v4] = a4;
        }
        __syncthreads();
        // ---- ctx reduce + z(ctx) (256 threads) ----
        if (tid < 256) {
            int r2 = tid >> 6, v = tid & 63;
            float cx = 0.f;
#pragma unroll
            for (int sl = 0; sl < 8; sl++) cx += sct[(r2 * 8 + sl) * 64 + v];
            sx1[r2 * 192 + v] = cx;
            size_t row = (size_t)(b0 + r2) * Lsteps + t;
            __nv_bfloat16 ch = __float2bfloat16(cx);
            g_zh[row * 128 + 64 + v] = ch;
            g_zl[row * 128 + 64 + v] = __float2bfloat16(cx - __bfloat162float(ch));
        }
        __syncthreads();
    }
}

// ================= launcher =================
extern "C" void kernel_launch(void* const* d_in, const int* in_sizes, int n_in,
                              void* d_out, int out_size) {
    const float* key    = (const float*)d_in[0];
    const float* values = (const float*)d_in[1];
    const float* mask   = (const float*)d_in[2];
    const int*   text   = (const int*)d_in[3];
    const float* emb    = (const float*)d_in[4];
    const float* Wih1   = (const float*)d_in[5];
    const float* Whh1   = (const float*)d_in[6];
    const float* bih1   = (const float*)d_in[7];
    const float* bhh1   = (const float*)d_in[8];
    const float* Wih2   = (const float*)d_in[9];
    const float* Whh2   = (const float*)d_in[10];
    const float* bih2   = (const float*)d_in[11];
    const float* bhh2   = (const float*)d_in[12];
    const float* Wq     = (const float*)d_in[13];
    const float* bq     = (const float*)d_in[14];
    const float* Wout   = (const float*)d_in[15];
    const float* bout   = (const float*)d_in[16];
    float* out = (float*)d_out;

    void *p_zEh, *p_zEl, *p_W1eh, *p_W1el, *p_b1p, *p_G1e;
    void *p_zh, *p_zl, *p_Woh, *p_Wol, *p_boutp;
    cudaGetSymbolAddress(&p_zEh, g_zEh);
    cudaGetSymbolAddress(&p_zEl, g_zEl);
    cudaGetSymbolAddress(&p_W1eh, g_W1eh);
    cudaGetSymbolAddress(&p_W1el, g_W1el);
    cudaGetSymbolAddress(&p_b1p, g_b1p);
    cudaGetSymbolAddress(&p_G1e, g_G1e);
    cudaGetSymbolAddress(&p_zh, g_zh);
    cudaGetSymbolAddress(&p_zl, g_zl);
    cudaGetSymbolAddress(&p_Woh, g_Woh);
    cudaGetSymbolAddress(&p_Wol, g_Wol);
    cudaGetSymbolAddress(&p_boutp, g_boutp);

    cudaFuncSetAttribute(k_gemm_mma, cudaFuncAttributeMaxDynamicSharedMemorySize, 104960);
    cudaFuncSetAttribute(k_recur2, cudaFuncAttributeMaxDynamicSharedMemorySize,
                         R_SMEM_FLOATS * 4);

    k_prep<<<256, 256>>>(Wih1, Whh1, bih1, bhh1, Wih2, Whh2, bih2, bhh2, Wq, Wout, bout);
    k_gather<<<256, 256>>>(text, emb);
    k_keyT<<<dim3(4, Bsz), 256>>>(key);

    // G1e = zE @ W1e^T + b1p   (M=14848, N=512, K=128)
    k_gemm_mma<<<dim3(512 / 128, NROW / 128), 256, 104960>>>(
        (const __nv_bfloat16*)p_zEh, (const __nv_bfloat16*)p_zEl,
        (const __nv_bfloat16*)p_W1eh, (const __nv_bfloat16*)p_W1el,
        (const float*)p_b1p, (float*)p_G1e, 512, 512);

    k_recur2<<<NCTA_R, 512, R_SMEM_FLOATS * 4>>>(values, mask, bq);

    // out = z @ Wout^T + bout  (M=14848, N=5000 padded 5120, K=128)
    k_gemm_mma<<<dim3(VPAD / 128, NROW / 128), 256, 104960>>>(
        (const __nv_bfloat16*)p_zh, (const __nv_bfloat16*)p_zl,
        (const __nv_bfloat16*)p_Woh, (const __nv_bfloat16*)p_Wol,
        (const float*)p_boutp, out, VOC, VOC);
}